// round 1
// baseline (speedup 1.0000x reference)
#include <cuda_runtime.h>

// Shapes: B=16, S=1024, D=1024. M = B*S = 16384.
#define MROWS 16384
#define NDIM  1024
#define BSD   16777216LL   // 16*1024*1024 elements per [B,S,D] buffer

// Scratch layout (float offsets, each slot = BSD):
// 0:qr 1:qi 2:kr 3:ki 4:vr 5:vi 6:scores/attn 7:out_r 8:out_i
__device__ float g_scratch[9ULL * 16777216ULL];

#define BM 128
#define BN 128
#define BK 8

// ---------------------------------------------------------------------------
// GEMM NT: C[m,n] (+)= alpha * sum_k A[m,k]*B[n,k]  (+ bias[n])
// A:[M,K] row-major, B:[N,K] row-major. Batched via blockIdx.z strides.
// ---------------------------------------------------------------------------
__global__ __launch_bounds__(256) void gemm_nt_k(
    const float* __restrict__ Aext, long long offA,
    const float* __restrict__ Bext, long long offB,
    const float* __restrict__ bias,
    long long offC,
    int M, int N, int K, float alpha, int accum,
    long long sA, long long sB, long long sC)
{
    const float* A = (Aext ? Aext : g_scratch + offA) + (long long)blockIdx.z * sA;
    const float* B = (Bext ? Bext : g_scratch + offB) + (long long)blockIdx.z * sB;
    float*       C = g_scratch + offC + (long long)blockIdx.z * sC;

    __shared__ float As[BK][BM];
    __shared__ float Bs[BK][BN];

    const int tid = threadIdx.x;
    const int bm = blockIdx.y * BM;
    const int bn = blockIdx.x * BN;

    const int lr = tid >> 1;          // 0..127
    const int lc = (tid & 1) << 2;    // 0 or 4
    const float* Ap = A + (long long)(bm + lr) * K + lc;
    const float* Bp = B + (long long)(bn + lr) * K + lc;

    const int ty = (tid >> 4) << 3;   // 0..120 step 8
    const int tx = (tid & 15) << 3;

    float acc[8][8];
#pragma unroll
    for (int i = 0; i < 8; i++)
#pragma unroll
        for (int j = 0; j < 8; j++) acc[i][j] = 0.f;

    for (int k0 = 0; k0 < K; k0 += BK) {
        float4 a = *(const float4*)(Ap + k0);
        float4 b = *(const float4*)(Bp + k0);
        __syncthreads();
        As[lc + 0][lr] = a.x; As[lc + 1][lr] = a.y; As[lc + 2][lr] = a.z; As[lc + 3][lr] = a.w;
        Bs[lc + 0][lr] = b.x; Bs[lc + 1][lr] = b.y; Bs[lc + 2][lr] = b.z; Bs[lc + 3][lr] = b.w;
        __syncthreads();
#pragma unroll
        for (int kk = 0; kk < BK; kk++) {
            float ra[8], rb[8];
#pragma unroll
            for (int i = 0; i < 8; i++) ra[i] = As[kk][ty + i];
#pragma unroll
            for (int j = 0; j < 8; j++) rb[j] = Bs[kk][tx + j];
#pragma unroll
            for (int i = 0; i < 8; i++)
#pragma unroll
                for (int j = 0; j < 8; j++)
                    acc[i][j] = fmaf(ra[i], rb[j], acc[i][j]);
        }
    }

#pragma unroll
    for (int i = 0; i < 8; i++) {
        long long row = bm + ty + i;
#pragma unroll
        for (int j = 0; j < 8; j++) {
            int col = bn + tx + j;
            float v = alpha * acc[i][j];
            if (bias) v += bias[col];
            float* cp = C + row * N + col;
            if (accum) v += *cp;
            *cp = v;
        }
    }
}

// ---------------------------------------------------------------------------
// GEMM NN: C[m,n] (+)= alpha * sum_k A[m,k]*B[k,n]
// ---------------------------------------------------------------------------
__global__ __launch_bounds__(256) void gemm_nn_k(
    const float* __restrict__ Aext, long long offA,
    const float* __restrict__ Bext, long long offB,
    long long offC,
    int M, int N, int K, float alpha, int accum,
    long long sA, long long sB, long long sC)
{
    const float* A = (Aext ? Aext : g_scratch + offA) + (long long)blockIdx.z * sA;
    const float* B = (Bext ? Bext : g_scratch + offB) + (long long)blockIdx.z * sB;
    float*       C = g_scratch + offC + (long long)blockIdx.z * sC;

    __shared__ float As[BK][BM];
    __shared__ float Bs[BK][BN];

    const int tid = threadIdx.x;
    const int bm = blockIdx.y * BM;
    const int bn = blockIdx.x * BN;

    const int lr = tid >> 1;
    const int lc = (tid & 1) << 2;
    const float* Ap = A + (long long)(bm + lr) * K + lc;

    const int lrB = tid >> 5;          // 0..7 (k-row of tile)
    const int lcB = (tid & 31) << 2;   // 0..124
    const float* Bp = B + (long long)lrB * N + bn + lcB;

    const int ty = (tid >> 4) << 3;
    const int tx = (tid & 15) << 3;

    float acc[8][8];
#pragma unroll
    for (int i = 0; i < 8; i++)
#pragma unroll
        for (int j = 0; j < 8; j++) acc[i][j] = 0.f;

    for (int k0 = 0; k0 < K; k0 += BK) {
        float4 a = *(const float4*)(Ap + k0);
        float4 b = *(const float4*)(Bp + (long long)k0 * N);
        __syncthreads();
        As[lc + 0][lr] = a.x; As[lc + 1][lr] = a.y; As[lc + 2][lr] = a.z; As[lc + 3][lr] = a.w;
        *(float4*)&Bs[lrB][lcB] = b;
        __syncthreads();
#pragma unroll
        for (int kk = 0; kk < BK; kk++) {
            float ra[8], rb[8];
#pragma unroll
            for (int i = 0; i < 8; i++) ra[i] = As[kk][ty + i];
#pragma unroll
            for (int j = 0; j < 8; j++) rb[j] = Bs[kk][tx + j];
#pragma unroll
            for (int i = 0; i < 8; i++)
#pragma unroll
                for (int j = 0; j < 8; j++)
                    acc[i][j] = fmaf(ra[i], rb[j], acc[i][j]);
        }
    }

#pragma unroll
    for (int i = 0; i < 8; i++) {
        long long row = bm + ty + i;
#pragma unroll
        for (int j = 0; j < 8; j++) {
            int col = bn + tx + j;
            float v = alpha * acc[i][j];
            float* cp = C + row * N + col;
            if (accum) v += *cp;
            *cp = v;
        }
    }
}

// ---------------------------------------------------------------------------
// Row softmax over 1024 cols, one block (256 threads) per row, in-place.
// ---------------------------------------------------------------------------
__global__ __launch_bounds__(256) void softmax_k(long long off)
{
    __shared__ float red[8];
    float* r = g_scratch + off + (long long)blockIdx.x * 1024;
    const int tid = threadIdx.x;

    float4 v = ((float4*)r)[tid];
    float m = fmaxf(fmaxf(v.x, v.y), fmaxf(v.z, v.w));
#pragma unroll
    for (int o = 16; o; o >>= 1) m = fmaxf(m, __shfl_xor_sync(0xffffffffu, m, o));
    if ((tid & 31) == 0) red[tid >> 5] = m;
    __syncthreads();
    float bm = red[0];
#pragma unroll
    for (int i = 1; i < 8; i++) bm = fmaxf(bm, red[i]);
    __syncthreads();

    v.x = __expf(v.x - bm); v.y = __expf(v.y - bm);
    v.z = __expf(v.z - bm); v.w = __expf(v.w - bm);
    float s = v.x + v.y + v.z + v.w;
#pragma unroll
    for (int o = 16; o; o >>= 1) s += __shfl_xor_sync(0xffffffffu, s, o);
    if ((tid & 31) == 0) red[tid >> 5] = s;
    __syncthreads();
    float bs = 0.f;
#pragma unroll
    for (int i = 0; i < 8; i++) bs += red[i];

    float inv = 1.0f / bs;
    v.x *= inv; v.y *= inv; v.z *= inv; v.w *= inv;
    ((float4*)r)[tid] = v;
}

// ---------------------------------------------------------------------------
// Complex LayerNorm over D=1024. z = out_r + i*out_i.
// mean/var in complex arithmetic, std = principal complex sqrt(var + eps),
// y = a2 * (z - mean)/std + b2.  out[0..BSD)=real, out[BSD..2BSD)=imag.
// ---------------------------------------------------------------------------
__global__ __launch_bounds__(256) void complex_ln_k(
    long long offR, long long offI,
    const float* __restrict__ a2, const float* __restrict__ b2,
    float* __restrict__ out)
{
    __shared__ float redA[8], redB[8];
    const long long row = blockIdx.x;
    const int tid = threadIdx.x;

    float4 zr = ((const float4*)(g_scratch + offR + row * 1024))[tid];
    float4 zi = ((const float4*)(g_scratch + offI + row * 1024))[tid];

    float sr = zr.x + zr.y + zr.z + zr.w;
    float si = zi.x + zi.y + zi.z + zi.w;
#pragma unroll
    for (int o = 16; o; o >>= 1) {
        sr += __shfl_xor_sync(0xffffffffu, sr, o);
        si += __shfl_xor_sync(0xffffffffu, si, o);
    }
    if ((tid & 31) == 0) { redA[tid >> 5] = sr; redB[tid >> 5] = si; }
    __syncthreads();
    float mr = 0.f, mi = 0.f;
#pragma unroll
    for (int i = 0; i < 8; i++) { mr += redA[i]; mi += redB[i]; }
    mr *= (1.f / 1024.f); mi *= (1.f / 1024.f);

    zr.x -= mr; zr.y -= mr; zr.z -= mr; zr.w -= mr;
    zi.x -= mi; zi.y -= mi; zi.z -= mi; zi.w -= mi;

    // complex (z-m)^2 summed: real = zr^2 - zi^2, imag = 2 zr zi
    float vr = (zr.x * zr.x - zi.x * zi.x) + (zr.y * zr.y - zi.y * zi.y)
             + (zr.z * zr.z - zi.z * zi.z) + (zr.w * zr.w - zi.w * zi.w);
    float vi = 2.f * (zr.x * zi.x + zr.y * zi.y + zr.z * zi.z + zr.w * zi.w);
    __syncthreads();
#pragma unroll
    for (int o = 16; o; o >>= 1) {
        vr += __shfl_xor_sync(0xffffffffu, vr, o);
        vi += __shfl_xor_sync(0xffffffffu, vi, o);
    }
    if ((tid & 31) == 0) { redA[tid >> 5] = vr; redB[tid >> 5] = vi; }
    __syncthreads();
    float cr = 0.f, ci = 0.f;
#pragma unroll
    for (int i = 0; i < 8; i++) { cr += redA[i]; ci += redB[i]; }
    cr = cr * (1.f / 1024.f) + 1e-6f;
    ci = ci * (1.f / 1024.f);

    // principal complex sqrt of c = cr + i*ci
    float rmod = sqrtf(cr * cr + ci * ci);
    float ssr = sqrtf(fmaxf(0.5f * (rmod + cr), 0.f));
    float ssi = copysignf(sqrtf(fmaxf(0.5f * (rmod - cr), 0.f)), ci);
    // z/std = z * conj(std) / |std|^2, and |sqrt(c)|^2 = |c| = rmod
    float inv = 1.f / rmod;

    float4 a4 = ((const float4*)a2)[tid];
    float4 b4 = ((const float4*)b2)[tid];

    float4 yr, yi;
    yr.x = (zr.x * ssr + zi.x * ssi) * inv;  yi.x = (zi.x * ssr - zr.x * ssi) * inv;
    yr.y = (zr.y * ssr + zi.y * ssi) * inv;  yi.y = (zi.y * ssr - zr.y * ssi) * inv;
    yr.z = (zr.z * ssr + zi.z * ssi) * inv;  yi.z = (zi.z * ssr - zr.z * ssi) * inv;
    yr.w = (zr.w * ssr + zi.w * ssi) * inv;  yi.w = (zi.w * ssr - zr.w * ssi) * inv;

    yr.x = a4.x * yr.x + b4.x;  yi.x = a4.x * yi.x;
    yr.y = a4.y * yr.y + b4.y;  yi.y = a4.y * yi.y;
    yr.z = a4.z * yr.z + b4.z;  yi.z = a4.z * yi.z;
    yr.w = a4.w * yr.w + b4.w;  yi.w = a4.w * yi.w;

    ((float4*)(out + row * 1024))[tid] = yr;
    ((float4*)(out + 16777216LL + row * 1024))[tid] = yi;
}

// ---------------------------------------------------------------------------
extern "C" void kernel_launch(void* const* d_in, const int* in_sizes, int n_in,
                              void* d_out, int out_size)
{
    const float* q_real = (const float*)d_in[0];
    const float* q_imag = (const float*)d_in[1];
    const float* k_real = (const float*)d_in[2];
    const float* k_imag = (const float*)d_in[3];
    const float* v_real = (const float*)d_in[4];
    const float* v_imag = (const float*)d_in[5];
    const float* Wq_r = (const float*)d_in[6];
    const float* bq_r = (const float*)d_in[7];
    const float* Wq_i = (const float*)d_in[8];
    const float* bq_i = (const float*)d_in[9];
    const float* Wk_r = (const float*)d_in[10];
    const float* bk_r = (const float*)d_in[11];
    const float* Wk_i = (const float*)d_in[12];
    const float* bk_i = (const float*)d_in[13];
    const float* Wv_r = (const float*)d_in[14];
    const float* bv_r = (const float*)d_in[15];
    const float* Wv_i = (const float*)d_in[16];
    const float* bv_i = (const float*)d_in[17];
    const float* a2   = (const float*)d_in[18];
    const float* b2   = (const float*)d_in[19];
    float* out = (float*)d_out;

    const long long L = 16777216LL;   // slot size (floats)
    const long long P = 1048576LL;    // per-batch stride S*D = S*S

    dim3 blk(256);
    dim3 gp(NDIM / BN, MROWS / BM, 1);   // (8, 128)

    // Projections: y = X @ W^T + b  -> scratch slots 0..5
    gemm_nt_k<<<gp, blk>>>(q_real, 0, Wq_r, 0, bq_r, 0 * L, MROWS, NDIM, NDIM, 1.f, 0, 0, 0, 0);
    gemm_nt_k<<<gp, blk>>>(q_imag, 0, Wq_i, 0, bq_i, 1 * L, MROWS, NDIM, NDIM, 1.f, 0, 0, 0, 0);
    gemm_nt_k<<<gp, blk>>>(k_real, 0, Wk_r, 0, bk_r, 2 * L, MROWS, NDIM, NDIM, 1.f, 0, 0, 0, 0);
    gemm_nt_k<<<gp, blk>>>(k_imag, 0, Wk_i, 0, bk_i, 3 * L, MROWS, NDIM, NDIM, 1.f, 0, 0, 0, 0);
    gemm_nt_k<<<gp, blk>>>(v_real, 0, Wv_r, 0, bv_r, 4 * L, MROWS, NDIM, NDIM, 1.f, 0, 0, 0, 0);
    gemm_nt_k<<<gp, blk>>>(v_imag, 0, Wv_i, 0, bv_i, 5 * L, MROWS, NDIM, NDIM, 1.f, 0, 0, 0, 0);

    dim3 gb(NDIM / BN, 1024 / BM, 16);   // (8, 8, 16) batched

    // scores = 0.125 * (qr @ kr  +  qi @ ki^T)   -> slot 6
    gemm_nn_k<<<gb, blk>>>(nullptr, 0 * L, nullptr, 2 * L, 6 * L, 1024, 1024, 1024, 0.125f, 0, P, P, P);
    gemm_nt_k<<<gb, blk>>>(nullptr, 1 * L, nullptr, 3 * L, nullptr, 6 * L, 1024, 1024, 1024, 0.125f, 1, P, P, P);

    // softmax rows (B*S = 16384 rows)
    softmax_k<<<16384, blk>>>(6 * L);

    // out_r = attn @ vr (slot 7), out_i = attn @ vi (slot 8)
    gemm_nn_k<<<gb, blk>>>(nullptr, 6 * L, nullptr, 4 * L, 7 * L, 1024, 1024, 1024, 1.f, 0, P, P, P);
    gemm_nn_k<<<gb, blk>>>(nullptr, 6 * L, nullptr, 5 * L, 8 * L, 1024, 1024, 1024, 1.f, 0, P, P, P);

    // complex layernorm -> d_out [2, B, S, D]
    complex_ln_k<<<16384, blk>>>(7 * L, 8 * L, a2, b2, out);
}